// round 12
// baseline (speedup 1.0000x reference)
#include <cuda_runtime.h>
#include <math.h>
#include <stdint.h>

// Problem constants
#define BB    8
#define CC    128
#define NN    65536
#define NOBJ  64

#define PBLK     512               // points per block (one 2KB strip per channel)
#define CGRP     16                // channels per tile
#define NTILE    (CC / CGRP)       // 8 tiles per block
#define TILE_W   (CGRP * PBLK)     // 8192 words = 32 KB per tile
#define THREADS1 512               // 16 warps; warp w owns segs 4w..4w+3
#define NWARP    16
#define NCHUNK   (NN / PBLK)       // 128
#define NCID     (BB * NCHUNK)     // 1024 blocks
#define OUTN     (BB * NOBJ * CC)  // 65536 outputs

// Global accumulator (float bit patterns), L2-resident 256 KB.
__device__ int g_acc[OUTN];

// ---- cp.async helpers -------------------------------------------------------
__device__ __forceinline__ void cp_async16(uint32_t dst, const void* src) {
    asm volatile("cp.async.cg.shared.global [%0], [%1], 16;\n" :: "r"(dst), "l"(src));
}
__device__ __forceinline__ void cp_commit() { asm volatile("cp.async.commit_group;\n"); }
template <int N> __device__ __forceinline__ void cp_wait() {
    asm volatile("cp.async.wait_group %0;\n" :: "n"(N));
}

// Monotone float-max join (commutative/associative -> deterministic).
// Init cell must be 0xFF800000 (-inf pattern).
__device__ __forceinline__ void atomic_fmax(int* a, float v) {
    if (v >= 0.0f) atomicMax(a, __float_as_int(v));
    else           atomicMin((unsigned int*)a, (unsigned int)__float_as_int(v));
}

__global__ void init_acc() {
    g_acc[blockIdx.x * 512 + threadIdx.x] = 0xFF800000;   // -inf
}

// ---------------------------------------------------------------------------
// Stage 1: channel-group tiles for DRAM row locality.
//   Tile g = channels [16g,16g+16) x ALL 512 points (32 KB): each channel row
//   is fetched as ONE 2KB contiguous burst (one HBM row activation) instead of
//   16 time-separated 128B visits — the round-11 bottleneck.
//   LOADS: cp.async 16B double-buffered; smem word(c,pt) =
//          c*512 + ((pt4 ^ (c&7))<<2) + (pt&3): STS conflict-free, gmem 512B
//          contiguous per warp op.
//   SORT (fused, 16 buckets = owner warp s>>2): entry = pt | (s&3)<<9.
//          Intra-bucket order race is erased by max().
//   COMPUTE: per tile, warp w walks its bucket 2 entries/iteration
//          (half-warp each, lane&15 = channel); 4 scalar accumulators;
//          shfl_xor(16) merge; 4 atomic_fmax per low-lane per tile.
//   Drain: wait_group 1 except final tile (wait_group 0).
// ---------------------------------------------------------------------------
extern __shared__ float dynbuf[];     // [2][TILE_W] = 64 KB

__global__ __launch_bounds__(THREADS1) void seg_max_stage1(
    const float* __restrict__ feat, const int* __restrict__ idx32)
{
    __shared__ int   Psm[NWARP + 1];
    __shared__ int   pos[NWARP];
    __shared__ unsigned short Esm[PBLK];
    __shared__ int   ok;

    const int tid  = threadIdx.x;
    const int lane = tid & 31;
    const int w    = tid >> 5;
    const int cid  = blockIdx.x;
    const int b    = cid >> 7;
    const float* fbase = feat + (size_t)b * CC * NN + (cid & 127) * PBLK;

    const uint32_t buf_u = (uint32_t)__cvta_generic_to_shared(dynbuf);

    auto prefetch = [&](int g) {
        const uint32_t base = buf_u + (uint32_t)((g & 1) * TILE_W * 4);
        #pragma unroll
        for (int k = 0; k < 4; ++k) {
            int i   = tid + k * THREADS1;       // 0..2047 16B slots
            int cl  = i >> 7;                   // local channel 0..15
            int pt4 = i & 127;                  // 16B group along points
            uint32_t dst = base +
                (uint32_t)((cl * PBLK + ((pt4 ^ (cl & 7)) << 2)) * 4);
            cp_async16(dst, fbase + (size_t)(g * CGRP + cl) * NN + pt4 * 4);
        }
        cp_commit();
    };
    prefetch(0);
    prefetch(1);

    // ---- fused prep: dtype probe + 16-bucket counting sort -----------------
    if (tid == 0) ok = 1;
    if (tid < NWARP) pos[tid] = 0;
    __syncthreads();
    if (tid < 256) {
        // int64 in [0,64) -> int32 view [v,0,...]; random int32 cannot keep
        // all 256 odd words zero. Reads words 0..511: safe under either dtype.
        int lo = idx32[2 * tid];
        int hi = idx32[2 * tid + 1];
        if (hi != 0 || lo < 0 || lo >= NOBJ) atomicAnd(&ok, 0);
    }
    __syncthreads();
    const int s = idx32[(size_t)(cid * PBLK + tid) * (ok ? 2 : 1)];
    const int bucket = s >> 2;                 // owner warp
    atomicAdd(&pos[bucket], 1);
    __syncthreads();
    if (tid < 32) {                            // warp-0 scan of 16 counts
        int v = (lane < NWARP) ? pos[lane] : 0;
        int inc = v;
        #pragma unroll
        for (int d = 1; d < 32; d <<= 1) {
            int t = __shfl_up_sync(0xffffffffu, inc, d);
            if (lane >= d) inc += t;
        }
        if (lane < NWARP) { Psm[lane] = inc - v; pos[lane] = inc - v; }
        if (lane == 0) Psm[NWARP] = PBLK;
    }
    __syncthreads();
    {
        int r = atomicAdd(&pos[bucket], 1);
        Esm[r] = (unsigned short)(tid | ((s & 3) << 9));
    }
    // Esm visibility: first barrier in the tile loop.

    const int i0 = Psm[w];
    const int i1 = Psm[w + 1];
    const int cl = lane & 15;
    int* accb = g_acc + (b * NOBJ + 4 * w) * CC + cl;   // + k*CC + 16*g

    for (int g = 0; g < NTILE; ++g) {
        if (g < NTILE - 1) cp_wait<1>(); else cp_wait<0>();
        __syncthreads();                       // tile g + (g==0: sort) visible

        const float* tb = dynbuf + (g & 1) * TILE_W;
        float r0 = -INFINITY, r1 = -INFINITY, r2 = -INFINITY, r3 = -INFINITY;

        for (int i = i0; i < i1; i += 2) {
            const unsigned e0 = Esm[i];
            const unsigned e1 = (i + 1 < i1) ? (unsigned)Esm[i + 1] : e0;
            const unsigned eh = (lane < 16) ? e0 : e1;   // per-half entry
            const int pt = eh & 511;
            const int sl = eh >> 9;
            const int a  = cl * PBLK + ((((pt >> 2) ^ (cl & 7))) << 2) + (pt & 3);
            const float v = tb[a];
            r0 = (sl == 0) ? fmaxf(r0, v) : r0;
            r1 = (sl == 1) ? fmaxf(r1, v) : r1;
            r2 = (sl == 2) ? fmaxf(r2, v) : r2;
            r3 = (sl == 3) ? fmaxf(r3, v) : r3;
        }

        // merge the two half-warps (they processed different entries)
        r0 = fmaxf(r0, __shfl_xor_sync(0xffffffffu, r0, 16));
        r1 = fmaxf(r1, __shfl_xor_sync(0xffffffffu, r1, 16));
        r2 = fmaxf(r2, __shfl_xor_sync(0xffffffffu, r2, 16));
        r3 = fmaxf(r3, __shfl_xor_sync(0xffffffffu, r3, 16));
        if (lane < 16) {
            int* ap = accb + g * CGRP;
            atomic_fmax(ap + 0 * CC, r0);
            atomic_fmax(ap + 1 * CC, r1);
            atomic_fmax(ap + 2 * CC, r2);
            atomic_fmax(ap + 3 * CC, r3);
        }

        __syncthreads();                       // buffer fully consumed
        if (g + 2 < NTILE) prefetch(g + 2);
    }
}

// ---------------------------------------------------------------------------
// Finalize: pattern -> float, -inf (empty segment) -> 0 guard.
// ---------------------------------------------------------------------------
__global__ void finalize_acc(float* __restrict__ out) {
    int i = blockIdx.x * 512 + threadIdx.x;
    float f = __int_as_float(g_acc[i]);
    out[i] = isfinite(f) ? f : 0.0f;
}

// ---------------------------------------------------------------------------
extern "C" void kernel_launch(void* const* d_in, const int* in_sizes, int n_in,
                              void* d_out, int out_size)
{
    const float* feat = nullptr;
    const int*   idx  = nullptr;
    for (int i = 0; i < n_in; ++i) {
        if (in_sizes[i] == BB * CC * NN)  feat = (const float*)d_in[i];
        else if (in_sizes[i] == BB * NN)  idx  = (const int*)d_in[i];
    }

    const int dyn = 2 * TILE_W * 4;            // 64 KB
    static int attr_set = 0;
    if (!attr_set) {
        cudaFuncSetAttribute(seg_max_stage1,
                             cudaFuncAttributeMaxDynamicSharedMemorySize, dyn);
        attr_set = 1;
    }

    init_acc<<<OUTN / 512, 512>>>();
    seg_max_stage1<<<NCID, THREADS1, dyn>>>(feat, idx);
    finalize_acc<<<OUTN / 512, 512>>>((float*)d_out);
}

// round 13
// speedup vs baseline: 1.3972x; 1.3972x over previous
#include <cuda_runtime.h>
#include <math.h>
#include <stdint.h>

// Problem constants
#define BB    8
#define CC    128
#define NN    65536
#define NOBJ  64

#define PBLK     512               // points per stage-1 block (chunk)
#define HT       32                // points per tile (128B rows)
#define NHT      (PBLK / HT)       // 16 tiles
#define DEPTH    3                 // pipeline depth
#define THREADS1 512               // 16 warps; warp w owns segs 4w..4w+3
#define NWARP    16
#define NCHUNK   (NN / PBLK)       // 128
#define NCID     (BB * NCHUNK)     // 1024 chunks
#define NBUCK    (NWARP * NHT)     // 256 buckets per chunk
#define TILE_W   (HT * CC)         // 4096 words per tile
#define OUTN     (BB * NOBJ * CC)  // 65536 outputs

// Scratch (static device arrays: allowed). __align__(16) for vector casts.
__device__ int g_acc[OUTN];                                            // 256 KB
__device__ __align__(16) unsigned short g_entries[NCID * PBLK];        // 1 MB
__device__ __align__(16) unsigned short g_pref[NCID * (NBUCK + 1)];    // 514 KB

// ---- cp.async helpers -------------------------------------------------------
__device__ __forceinline__ void cp_async16(uint32_t dst, const void* src) {
    asm volatile("cp.async.cg.shared.global [%0], [%1], 16;\n" :: "r"(dst), "l"(src));
}
__device__ __forceinline__ void cp_commit() { asm volatile("cp.async.commit_group;\n"); }
template <int N> __device__ __forceinline__ void cp_wait() {
    asm volatile("cp.async.wait_group %0;\n" :: "n"(N));
}

// Monotone float-max join (commutative/associative -> deterministic).
// Init cell must be 0xFF800000 (-inf pattern).
__device__ __forceinline__ void atomic_fmax(int* a, float v) {
    if (v >= 0.0f) atomicMax(a, __float_as_int(v));
    else           atomicMin((unsigned int*)a, (unsigned int)__float_as_int(v));
}

// ---------------------------------------------------------------------------
// Prep (separate kernel — measured cheaper than fusing the sort into stage-1):
// dtype-probe box_idx (int32 vs int64), counting-sort each chunk's 512 points
// into 256 buckets keyed (owner_warp = s>>2, tile = pt>>5); entry =
// pt | (s&3)<<9. Also initializes g_acc to -inf (64 cells per block), safe
// because stage-1 launches strictly after prep completes.
// ---------------------------------------------------------------------------
__global__ void prep_sort(const int* __restrict__ idx32) {
    __shared__ int ok;
    __shared__ int hist[NBUCK];
    __shared__ int wsum[8];
    __shared__ int pos[NBUCK];

    const int tid = threadIdx.x;          // 256
    const int cid = blockIdx.x;           // 1024 chunks

    // fused init of the global accumulator (64 cells per block)
    if (tid < 64) g_acc[cid * 64 + tid] = 0xFF800000;   // -inf pattern

    if (tid == 0) ok = 1;
    hist[tid] = 0;
    __syncthreads();
    {   // int64 in [0,64) -> int32 view [v,0,v,0,...]; random int32 can't
        // keep all 256 odd words zero -> unambiguous.
        int lo = idx32[2 * tid];
        int hi = idx32[2 * tid + 1];
        if (hi != 0 || lo < 0 || lo >= NOBJ) atomicAnd(&ok, 0);
    }
    __syncthreads();
    const int stride = ok ? 2 : 1;

    const int p0 = tid, p1 = tid + 256;   // two points per thread
    int s0 = idx32[(size_t)(cid * PBLK + p0) * stride];
    int s1 = idx32[(size_t)(cid * PBLK + p1) * stride];
    int b0 = (s0 >> 2) * NHT + (p0 >> 5);
    int b1 = (s1 >> 2) * NHT + (p1 >> 5);
    atomicAdd(&hist[b0], 1);
    atomicAdd(&hist[b1], 1);
    __syncthreads();

    // exclusive scan over hist[256]
    const int lane = tid & 31, wid = tid >> 5;
    int v = hist[tid];
    int inc = v;
    #pragma unroll
    for (int d = 1; d < 32; d <<= 1) {
        int t = __shfl_up_sync(0xffffffffu, inc, d);
        if (lane >= d) inc += t;
    }
    if (lane == 31) wsum[wid] = inc;
    __syncthreads();
    if (tid == 0) {
        int run = 0;
        #pragma unroll
        for (int i = 0; i < 8; ++i) { int t = wsum[i]; wsum[i] = run; run += t; }
    }
    __syncthreads();
    int exc = inc - v + wsum[wid];
    pos[tid] = exc;
    g_pref[cid * (NBUCK + 1) + tid] = (unsigned short)exc;
    if (tid == 0) g_pref[cid * (NBUCK + 1) + NBUCK] = (unsigned short)PBLK;
    __syncthreads();

    int r0 = atomicAdd(&pos[b0], 1);
    g_entries[cid * PBLK + r0] = (unsigned short)(p0 | ((s0 & 3) << 9));
    int r1 = atomicAdd(&pos[b1], 1);
    g_entries[cid * PBLK + r1] = (unsigned short)(p1 | ((s1 & 3) << 9));
}

// ---------------------------------------------------------------------------
// Stage 1: the measured-best core (rounds 4/6), depth-3, atomic output.
//   LOADS: cp.async 16B, channel-major tile [128c][32pt], 16B-granule swizzle
//          word(c,g) = c*32 + ((g ^ (c&7))<<2); coalesced gmem (4 lines/op).
//   COMPUTE: warp w owns segs 4w..4w+3; lane owns chans {l,l+32,l+64,l+96};
//          16 register accumulators, predicated FMAX, sorted-entry walk.
//   OUTPUT: 16 atomic_fmax per thread into g_acc (no partials, no stage-2).
//   Drain: group t complete at iter t -> wait_group min(DEPTH-1, NHT-1-t).
// ---------------------------------------------------------------------------
extern __shared__ float dynbuf[];     // [DEPTH][TILE_W] = 48 KB

__global__ __launch_bounds__(THREADS1) void seg_max_stage1(
    const float* __restrict__ feat)
{
    __shared__ unsigned short Psm[NBUCK + 2];
    __shared__ unsigned short Esm[PBLK];

    const int tid  = threadIdx.x;
    const int lane = tid & 31;
    const int w    = tid >> 5;
    const int cid  = blockIdx.x;
    const float* fbase = feat + (size_t)(cid >> 7) * CC * NN + (cid & 127) * PBLK;

    const uint32_t buf_u = (uint32_t)__cvta_generic_to_shared(dynbuf);

    auto prefetch = [&](int t) {
        const uint32_t base = buf_u + (uint32_t)((t % DEPTH) * TILE_W * 4);
        const float* sb = fbase + t * HT;
        #pragma unroll
        for (int k = 0; k < 2; ++k) {
            int i = tid + k * THREADS1;          // 0..1023 16B slots
            int c = i >> 3;                      // channel row 0..127
            int g = i & 7;                       // 16B granule in row
            cp_async16(base + (uint32_t)((c * 32 + ((g ^ (c & 7)) << 2)) * 4),
                       sb + (size_t)c * NN + g * 4);
        }
        cp_commit();
    };
    prefetch(0);
    prefetch(1);
    prefetch(2);

    if (tid < NBUCK + 1) Psm[tid] = g_pref[cid * (NBUCK + 1) + tid];
    if (tid < PBLK / 2)
        ((uint32_t*)Esm)[tid] = ((const uint32_t*)(g_entries + cid * PBLK))[tid];

    float r0[4], r1[4], r2[4], r3[4];
    #pragma unroll
    for (int k = 0; k < 4; ++k) {
        r0[k] = -INFINITY; r1[k] = -INFINITY;
        r2[k] = -INFINITY; r3[k] = -INFINITY;
    }

    for (int t = 0; t < NHT; ++t) {
        if      (t < NHT - 2) cp_wait<2>();
        else if (t < NHT - 1) cp_wait<1>();
        else                  cp_wait<0>();
        __syncthreads();                         // tile t + Psm/Esm visible

        const float* tb = dynbuf + (t % DEPTH) * TILE_W;
        const int i0 = Psm[w * NHT + t];
        const int i1 = Psm[w * NHT + t + 1];
        for (int i = i0; i < i1; ++i) {          // warp-uniform walk
            const unsigned e  = Esm[i];          // broadcast
            const int lp = e & 31;               // local point in tile
            const int sl = (e >> 9) & 3;         // warp-uniform 0..3
            const int a  = lane * 32 + (((lp >> 2) ^ (lane & 7)) << 2) + (lp & 3);
            float v0 = tb[a];
            float v1 = tb[a + 1024];
            float v2 = tb[a + 2048];
            float v3 = tb[a + 3072];
            r0[0] = (sl == 0) ? fmaxf(r0[0], v0) : r0[0];
            r0[1] = (sl == 0) ? fmaxf(r0[1], v1) : r0[1];
            r0[2] = (sl == 0) ? fmaxf(r0[2], v2) : r0[2];
            r0[3] = (sl == 0) ? fmaxf(r0[3], v3) : r0[3];
            r1[0] = (sl == 1) ? fmaxf(r1[0], v0) : r1[0];
            r1[1] = (sl == 1) ? fmaxf(r1[1], v1) : r1[1];
            r1[2] = (sl == 1) ? fmaxf(r1[2], v2) : r1[2];
            r1[3] = (sl == 1) ? fmaxf(r1[3], v3) : r1[3];
            r2[0] = (sl == 2) ? fmaxf(r2[0], v0) : r2[0];
            r2[1] = (sl == 2) ? fmaxf(r2[1], v1) : r2[1];
            r2[2] = (sl == 2) ? fmaxf(r2[2], v2) : r2[2];
            r2[3] = (sl == 2) ? fmaxf(r2[3], v3) : r2[3];
            r3[0] = (sl == 3) ? fmaxf(r3[0], v0) : r3[0];
            r3[1] = (sl == 3) ? fmaxf(r3[1], v1) : r3[1];
            r3[2] = (sl == 3) ? fmaxf(r3[2], v2) : r3[2];
            r3[3] = (sl == 3) ? fmaxf(r3[3], v3) : r3[3];
        }
        __syncthreads();                         // buffer fully consumed
        if (t + DEPTH < NHT) prefetch(t + DEPTH);
    }

    // Fold accumulators into the global joint max (deterministic).
    int* accp = g_acc + ((cid >> 7) * NOBJ + 4 * w) * CC + lane;
    #pragma unroll
    for (int k = 0; k < 4; ++k) {
        atomic_fmax(accp + 0 * CC + 32 * k, r0[k]);
        atomic_fmax(accp + 1 * CC + 32 * k, r1[k]);
        atomic_fmax(accp + 2 * CC + 32 * k, r2[k]);
        atomic_fmax(accp + 3 * CC + 32 * k, r3[k]);
    }
}

// ---------------------------------------------------------------------------
// Finalize: pattern -> float, -inf (empty segment) -> 0 guard.
// ---------------------------------------------------------------------------
__global__ void finalize_acc(float* __restrict__ out) {
    int i = blockIdx.x * 512 + threadIdx.x;
    float f = __int_as_float(g_acc[i]);
    out[i] = isfinite(f) ? f : 0.0f;
}

// ---------------------------------------------------------------------------
extern "C" void kernel_launch(void* const* d_in, const int* in_sizes, int n_in,
                              void* d_out, int out_size)
{
    const float* feat = nullptr;
    const int*   idx  = nullptr;
    for (int i = 0; i < n_in; ++i) {
        if (in_sizes[i] == BB * CC * NN)  feat = (const float*)d_in[i];
        else if (in_sizes[i] == BB * NN)  idx  = (const int*)d_in[i];
    }

    const int dyn = DEPTH * TILE_W * 4;          // 48 KB
    static int attr_set = 0;
    if (!attr_set) {
        cudaFuncSetAttribute(seg_max_stage1,
                             cudaFuncAttributeMaxDynamicSharedMemorySize, dyn);
        attr_set = 1;
    }

    prep_sort<<<NCID, 256>>>(idx);
    seg_max_stage1<<<NCID, THREADS1, dyn>>>(feat);
    finalize_acc<<<OUTN / 512, 512>>>((float*)d_out);
}

// round 14
// speedup vs baseline: 1.5196x; 1.0876x over previous
#include <cuda_runtime.h>
#include <math.h>
#include <stdint.h>

// Problem constants
#define BB    8
#define CC    128
#define NN    65536
#define NOBJ  64

#define PBLK     512               // points per stage-1 block (chunk)
#define HT       64                // points per tile (256B per channel-row visit)
#define NHT      (PBLK / HT)       // 8 tiles
#define DEPTH    2                 // pipeline depth (2 x 32KB = 64KB)
#define THREADS1 512               // 16 warps; warp w owns segs 4w..4w+3
#define NWARP    16
#define NCHUNK   (NN / PBLK)       // 128
#define NCID     (BB * NCHUNK)     // 1024 chunks
#define NBUCK    (NWARP * NHT)     // 128 buckets per chunk
#define TILE_W   (HT * CC)         // 8192 words per tile
#define OUTN     (BB * NOBJ * CC)  // 65536 outputs

// Scratch (static device arrays: allowed). __align__(16) for vector casts.
__device__ int g_acc[OUTN];                                            // 256 KB
__device__ __align__(16) unsigned short g_entries[NCID * PBLK];        // 1 MB
__device__ __align__(16) unsigned short g_pref[NCID * (NBUCK + 1)];    // 258 KB

// ---- cp.async helpers -------------------------------------------------------
__device__ __forceinline__ void cp_async16(uint32_t dst, const void* src) {
    asm volatile("cp.async.cg.shared.global [%0], [%1], 16;\n" :: "r"(dst), "l"(src));
}
__device__ __forceinline__ void cp_commit() { asm volatile("cp.async.commit_group;\n"); }
template <int N> __device__ __forceinline__ void cp_wait() {
    asm volatile("cp.async.wait_group %0;\n" :: "n"(N));
}

// Monotone float-max join (commutative/associative -> deterministic).
// Init cell must be 0xFF800000 (-inf pattern).
__device__ __forceinline__ void atomic_fmax(int* a, float v) {
    if (v >= 0.0f) atomicMax(a, __float_as_int(v));
    else           atomicMin((unsigned int*)a, (unsigned int)__float_as_int(v));
}

// ---------------------------------------------------------------------------
// Prep: dtype-probe box_idx, counting-sort each chunk's 512 points into 128
// buckets keyed (owner_warp = s>>2, tile = pt>>6); entry = pt | (s&3)<<9.
// Also initializes g_acc (-inf); safe: stage-1 launches strictly after prep.
// ---------------------------------------------------------------------------
__global__ void prep_sort(const int* __restrict__ idx32) {
    __shared__ int ok;
    __shared__ int hist[NBUCK];
    __shared__ int wsum[4];
    __shared__ int pos[NBUCK];

    const int tid = threadIdx.x;          // 256
    const int cid = blockIdx.x;           // 1024 chunks

    if (tid < 64) g_acc[cid * 64 + tid] = 0xFF800000;   // fused init (-inf)

    if (tid == 0) ok = 1;
    if (tid < NBUCK) hist[tid] = 0;
    __syncthreads();
    {   // int64 in [0,64) -> int32 view [v,0,v,0,...]; random int32 can't
        // keep all 256 odd words zero -> unambiguous.
        int lo = idx32[2 * tid];
        int hi = idx32[2 * tid + 1];
        if (hi != 0 || lo < 0 || lo >= NOBJ) atomicAnd(&ok, 0);
    }
    __syncthreads();
    const int stride = ok ? 2 : 1;

    const int p0 = tid, p1 = tid + 256;   // two points per thread
    int s0 = idx32[(size_t)(cid * PBLK + p0) * stride];
    int s1 = idx32[(size_t)(cid * PBLK + p1) * stride];
    int b0 = (s0 >> 2) * NHT + (p0 >> 6);
    int b1 = (s1 >> 2) * NHT + (p1 >> 6);
    atomicAdd(&hist[b0], 1);
    atomicAdd(&hist[b1], 1);
    __syncthreads();

    // exclusive scan over hist[128] (warps 0..3, fully active)
    const int lane = tid & 31, wid = tid >> 5;
    int v = 0, inc = 0;
    if (tid < NBUCK) {
        v = hist[tid];
        inc = v;
        #pragma unroll
        for (int d = 1; d < 32; d <<= 1) {
            int t = __shfl_up_sync(0xffffffffu, inc, d);
            if (lane >= d) inc += t;
        }
        if (lane == 31) wsum[wid] = inc;
    }
    __syncthreads();
    if (tid == 0) {
        int run = 0;
        #pragma unroll
        for (int i = 0; i < 4; ++i) { int t = wsum[i]; wsum[i] = run; run += t; }
    }
    __syncthreads();
    if (tid < NBUCK) {
        int exc = inc - v + wsum[wid];
        pos[tid] = exc;
        g_pref[cid * (NBUCK + 1) + tid] = (unsigned short)exc;
    }
    if (tid == 0) g_pref[cid * (NBUCK + 1) + NBUCK] = (unsigned short)PBLK;
    __syncthreads();

    int r0 = atomicAdd(&pos[b0], 1);
    g_entries[cid * PBLK + r0] = (unsigned short)(p0 | ((s0 & 3) << 9));
    int r1 = atomicAdd(&pos[b1], 1);
    g_entries[cid * PBLK + r1] = (unsigned short)(p1 | ((s1 & 3) << 9));
}

// ---------------------------------------------------------------------------
// Stage 1: round-13 core with HT=64 tiles (single-variable DRAM-granularity
// test: each channel row now fetched in 256B contiguous visits, 8 per block
// instead of 16 x 128B).
//   LOADS: cp.async 16B, channel-major tile [128c][64pt], 16B-granule swizzle
//          word(c,g) = c*64 + ((g ^ (c&15))<<2); warp op = 2 rows x 256B.
//   COMPUTE: identical sorted-entry walk, 16 register accumulators,
//          gather conflict degree unchanged (4-way).
//   OUTPUT: 16 atomic_fmax per thread into g_acc.
//   Drain: wait_group 1 except final tile (wait_group 0).
// ---------------------------------------------------------------------------
extern __shared__ float dynbuf[];     // [DEPTH][TILE_W] = 64 KB

__global__ __launch_bounds__(THREADS1) void seg_max_stage1(
    const float* __restrict__ feat)
{
    __shared__ unsigned short Psm[NBUCK + 2];
    __shared__ unsigned short Esm[PBLK];

    const int tid  = threadIdx.x;
    const int lane = tid & 31;
    const int w    = tid >> 5;
    const int cid  = blockIdx.x;
    const float* fbase = feat + (size_t)(cid >> 7) * CC * NN + (cid & 127) * PBLK;

    const uint32_t buf_u = (uint32_t)__cvta_generic_to_shared(dynbuf);

    auto prefetch = [&](int t) {
        const uint32_t base = buf_u + (uint32_t)((t & 1) * TILE_W * 4);
        const float* sb = fbase + t * HT;
        #pragma unroll
        for (int k = 0; k < 4; ++k) {
            int i = tid + k * THREADS1;          // 0..2047 16B slots
            int c = i >> 4;                      // channel row 0..127
            int g = i & 15;                      // 16B granule in row
            cp_async16(base + (uint32_t)((c * HT + ((g ^ (c & 15)) << 2)) * 4),
                       sb + (size_t)c * NN + g * 4);
        }
        cp_commit();
    };
    prefetch(0);
    prefetch(1);

    if (tid < NBUCK + 1) Psm[tid] = g_pref[cid * (NBUCK + 1) + tid];
    if (tid < PBLK / 2)
        ((uint32_t*)Esm)[tid] = ((const uint32_t*)(g_entries + cid * PBLK))[tid];

    float r0[4], r1[4], r2[4], r3[4];
    #pragma unroll
    for (int k = 0; k < 4; ++k) {
        r0[k] = -INFINITY; r1[k] = -INFINITY;
        r2[k] = -INFINITY; r3[k] = -INFINITY;
    }

    for (int t = 0; t < NHT; ++t) {
        if (t < NHT - 1) cp_wait<1>(); else cp_wait<0>();
        __syncthreads();                         // tile t + Psm/Esm visible

        const float* tb = dynbuf + (t & 1) * TILE_W;
        const int i0 = Psm[w * NHT + t];
        const int i1 = Psm[w * NHT + t + 1];
        for (int i = i0; i < i1; ++i) {          // warp-uniform walk
            const unsigned e  = Esm[i];          // broadcast
            const int lp = e & 63;               // local point in tile
            const int sl = (e >> 9) & 3;         // warp-uniform 0..3
            const int a  = lane * HT
                         + ((((lp >> 2) & 15) ^ (lane & 15)) << 2) + (lp & 3);
            float v0 = tb[a];
            float v1 = tb[a + 32 * HT];
            float v2 = tb[a + 64 * HT];
            float v3 = tb[a + 96 * HT];
            r0[0] = (sl == 0) ? fmaxf(r0[0], v0) : r0[0];
            r0[1] = (sl == 0) ? fmaxf(r0[1], v1) : r0[1];
            r0[2] = (sl == 0) ? fmaxf(r0[2], v2) : r0[2];
            r0[3] = (sl == 0) ? fmaxf(r0[3], v3) : r0[3];
            r1[0] = (sl == 1) ? fmaxf(r1[0], v0) : r1[0];
            r1[1] = (sl == 1) ? fmaxf(r1[1], v1) : r1[1];
            r1[2] = (sl == 1) ? fmaxf(r1[2], v2) : r1[2];
            r1[3] = (sl == 1) ? fmaxf(r1[3], v3) : r1[3];
            r2[0] = (sl == 2) ? fmaxf(r2[0], v0) : r2[0];
            r2[1] = (sl == 2) ? fmaxf(r2[1], v1) : r2[1];
            r2[2] = (sl == 2) ? fmaxf(r2[2], v2) : r2[2];
            r2[3] = (sl == 2) ? fmaxf(r2[3], v3) : r2[3];
            r3[0] = (sl == 3) ? fmaxf(r3[0], v0) : r3[0];
            r3[1] = (sl == 3) ? fmaxf(r3[1], v1) : r3[1];
            r3[2] = (sl == 3) ? fmaxf(r3[2], v2) : r3[2];
            r3[3] = (sl == 3) ? fmaxf(r3[3], v3) : r3[3];
        }
        __syncthreads();                         // buffer fully consumed
        if (t + DEPTH < NHT) prefetch(t + DEPTH);
    }

    // Fold accumulators into the global joint max (deterministic).
    int* accp = g_acc + ((cid >> 7) * NOBJ + 4 * w) * CC + lane;
    #pragma unroll
    for (int k = 0; k < 4; ++k) {
        atomic_fmax(accp + 0 * CC + 32 * k, r0[k]);
        atomic_fmax(accp + 1 * CC + 32 * k, r1[k]);
        atomic_fmax(accp + 2 * CC + 32 * k, r2[k]);
        atomic_fmax(accp + 3 * CC + 32 * k, r3[k]);
    }
}

// ---------------------------------------------------------------------------
// Finalize: pattern -> float, -inf (empty segment) -> 0 guard.
// ---------------------------------------------------------------------------
__global__ void finalize_acc(float* __restrict__ out) {
    int i = blockIdx.x * 512 + threadIdx.x;
    float f = __int_as_float(g_acc[i]);
    out[i] = isfinite(f) ? f : 0.0f;
}

// ---------------------------------------------------------------------------
extern "C" void kernel_launch(void* const* d_in, const int* in_sizes, int n_in,
                              void* d_out, int out_size)
{
    const float* feat = nullptr;
    const int*   idx  = nullptr;
    for (int i = 0; i < n_in; ++i) {
        if (in_sizes[i] == BB * CC * NN)  feat = (const float*)d_in[i];
        else if (in_sizes[i] == BB * NN)  idx  = (const int*)d_in[i];
    }

    const int dyn = DEPTH * TILE_W * 4;          // 64 KB
    static int attr_set = 0;
    if (!attr_set) {
        cudaFuncSetAttribute(seg_max_stage1,
                             cudaFuncAttributeMaxDynamicSharedMemorySize, dyn);
        attr_set = 1;
    }

    prep_sort<<<NCID, 256>>>(idx);
    seg_max_stage1<<<NCID, THREADS1, dyn>>>(feat);
    finalize_acc<<<OUTN / 512, 512>>>((float*)d_out);
}